// round 7
// baseline (speedup 1.0000x reference)
#include <cuda_runtime.h>
#include <cstdint>
#include <cstddef>

// Problem constants (fixed shapes for this dataset)
#define NN     4096     // N*N
#define NCOL   64       // N
#define CC     256      // feature dim
#define BB     32       // batch (videos)
#define SS     64       // sentences
#define PT     128      // proposals per block tile
#define KC     64       // K-chunk of sentence data staged in smem
#define TPB2   256      // threads in score kernel
#define MAXT   (NN/PT)  // worst-case tiles (32)
#define CHN    (CC/KC)  // 4 chunks
#define NITEM  (BB*MAXT)

#define INV_T 10.0f     // 1 / 0.1
#define EPSN  1e-12f

// ---------------- device scratch (no allocations allowed) ----------------
// g_flat: aligned-quad compaction. Entry = flat index if valid, ~flat if pad.
// Quad bases are multiples of 4 -> 16B-aligned video loads, pads in-bounds.
__device__ int   g_flat[NN];
__device__ int   g_P;                   // padded proposal count
__device__ int   g_scatter[SS];         // sentence -> video index
__device__ float g_sf[SS*CC];           // normalized sentence feats [s][c]
__device__ __align__(16) unsigned long long g_sfD[CC*SS]; // dup pairs [c][s]
__device__ float g_partial[SS*NITEM];   // [s][item] partial neg-exp sums
__device__ float g_negsum[SS];          // inter-query neg sums
__device__ int   g_pstar[SS];           // per-sentence argmax proposal
__device__ float g_A[SS*SS];            // A[s][t] = dot(topk_video[s], sf[t])

// packed fp32x2 helpers (SASS FFMA2 — only reachable via PTX)
__device__ __forceinline__ void ffma2(unsigned long long& acc,
                                      unsigned long long w,
                                      unsigned long long v) {
    asm("fma.rn.f32x2 %0, %1, %2, %0;" : "+l"(acc) : "l"(w), "l"(v));
}
__device__ __forceinline__ unsigned long long pack2(float x) {
    unsigned long long r;
    asm("mov.b64 %0, {%1, %1};" : "=l"(r) : "r"(__float_as_uint(x)));
    return r;
}
__device__ __forceinline__ float unpack_lo(unsigned long long u) {
    return __uint_as_float((unsigned)(u & 0xffffffffu));
}
__device__ __forceinline__ float unpack_hi(unsigned long long u) {
    return __uint_as_float((unsigned)(u >> 32));
}
__device__ __forceinline__ void cp_async16(uint32_t saddr, const void* gptr) {
    asm volatile("cp.async.cg.shared.global [%0], [%1], 16;"
                 :: "r"(saddr), "l"(gptr) : "memory");
}

// ---------------- setup: aligned-quad mask compaction + scatter ----------
// Per mask row: find [first,last] valid columns, start at first&~3, pad count
// to a multiple of 4. Entries carry validity in the sign bit (~flat = pad).
__global__ void setup_kernel(const unsigned char* __restrict__ mask,
                             const int* __restrict__ num_targets) {
    __shared__ int rowstart[NCOL];
    __shared__ int rowcnt[NCOL];
    __shared__ int rowlast[NCOL];
    __shared__ int rowbase[NCOL];
    __shared__ int mode_s;
    int t = threadIdx.x;                  // 1024 threads
    if (t == 0) mode_s = (mask[1] != 0);  // byte-bool vs 4-byte encoding
    __syncthreads();
    int mode = mode_s;

    int r   = t >> 4;                     // row 0..63
    int seg = t & 15;                     // 16 threads per row
    int bcol = seg * 4;

    int vmask = 0;                        // 4 validity bits for my columns
#pragma unroll
    for (int k = 0; k < 4; k++) {
        int idx = r * NCOL + bcol + k;
        int m = mode ? (mask[idx] != 0)
                     : (((const int*)mask)[idx] != 0);
        vmask |= m << k;
    }
    // local first/last valid col (or +inf / -inf)
    int lfirst = 1 << 20, llast = -1;
#pragma unroll
    for (int k = 0; k < 4; k++) {
        if (vmask & (1 << k)) {
            if (bcol + k < lfirst) lfirst = bcol + k;
            llast = bcol + k;
        }
    }
    // segment (width-16) min/max
#pragma unroll
    for (int off = 8; off; off >>= 1) {
        int a = __shfl_down_sync(0xffffffffu, lfirst, off, 16);
        int bmx = __shfl_down_sync(0xffffffffu, llast, off, 16);
        lfirst = min(lfirst, a);
        llast  = max(llast, bmx);
    }
    if (seg == 0) {
        if (llast < 0) { rowstart[r] = 0; rowcnt[r] = 0; rowlast[r] = -1; }
        else {
            int st = lfirst & ~3;
            rowstart[r] = st;
            rowcnt[r]   = (llast + 1 - st + 3) & ~3;
            rowlast[r]  = llast;
        }
    }
    __syncthreads();
    if (t == 0) {
        int acc = 0;
        for (int i = 0; i < NCOL; i++) { rowbase[i] = acc; acc += rowcnt[i]; }
        g_P = acc;
    }
    __syncthreads();

    // write entries: 16 threads cover up to 64 slots per row
    int cnt = rowcnt[r], st = rowstart[r], base = rowbase[r];
#pragma unroll
    for (int k = 0; k < 4; k++) {
        int j = bcol + k;
        if (j < cnt) {
            int col  = st + j;
            int flat = r * NCOL + col;
            int m;
            if (col < NCOL) {
                m = mode ? (mask[flat] != 0) : (((const int*)mask)[flat] != 0);
            } else { m = 0; flat = r * NCOL + NCOL - 1; }  // clamp (in-bounds)
            g_flat[base + j] = m ? flat : ~flat;
        }
    }

    if (t == 0) {
        int off = 0;
        for (int b = 0; b < BB && off < SS; b++) {
            int n = num_targets[b];
            for (int k = 0; k < n && off < SS; k++) g_scatter[off++] = b;
        }
    }
}

// ---------------- prep: normalize sentences + per-sentence iou argmax ----
__global__ void prep_kernel(const float* __restrict__ sents,
                            const float* __restrict__ iou) {
    int s = blockIdx.x, t = threadIdx.x;   // SS blocks x 256 threads
    __shared__ float sm[256];
    float x = sents[s * CC + t];
    sm[t] = x * x;
    __syncthreads();
    for (int st = 128; st > 0; st >>= 1) {
        if (t < st) sm[t] += sm[t + st];
        __syncthreads();
    }
    float inv = 1.0f / fmaxf(sqrtf(sm[0]), EPSN);
    float v = x * inv;
    g_sf[s * CC + t]  = v;
    g_sfD[t * SS + s] = pack2(v);

    // argmax over gathered iou (first-max-kept; pads skipped)
    int P = g_P;
    __shared__ float bv[256];
    __shared__ int   bi[256];
    float best = -1e30f;
    int bp = 1 << 30;
    for (int p = t; p < P; p += 256) {
        int g = g_flat[p];
        float vv = (g >= 0) ? iou[s * NN + g] : -1e30f;
        if (vv > best) { best = vv; bp = p; }
    }
    bv[t] = best; bi[t] = bp;
    __syncthreads();
    for (int st = 128; st > 0; st >>= 1) {
        if (t < st) {
            if (bv[t + st] > bv[t] || (bv[t + st] == bv[t] && bi[t + st] < bi[t])) {
                bv[t] = bv[t + st]; bi[t] = bi[t + st];
            }
        }
        __syncthreads();
    }
    if (t == 0) g_pstar[s] = g_flat[bi[0]];
}

// ---------------- main fused score kernel ----------------
// 128p x 64s block tile. Video read DIRECTLY from global as 16B-aligned
// contiguous float4 quads (aligned-quad compaction) — no vt smem, no
// conditional loads. Sentence pairs cp.async double-buffered, KC=64.
// Thread (tp=tid&15, ts=tid>>4): 8 proposals (two quads), 4 sentences.
// Per k: 2 LDG.128 + 2 LDS.128 (broadcast) + 20 FFMA2 (16 acc + 4 ssq).
__global__ __launch_bounds__(TPB2, 3)
void score_kernel(const float* __restrict__ video,
                  const float* __restrict__ iou) {
    const int P = g_P;
    const int tile = blockIdx.x;
    const int tbase = tile * PT;
    if (tbase >= P) return;                // dead padding tile
    const int b = blockIdx.y;

    extern __shared__ float smem[];
    unsigned long long* sfb0 = (unsigned long long*)smem;   // [KC][SS] 32KB
    unsigned long long* sfb1 = sfb0 + KC * SS;              // 32KB
    __shared__ int scat[SS];
    __shared__ int gflat_s[PT];

    const int tid = threadIdx.x;
    if (tid < SS) scat[tid] = g_scatter[tid];
    if (tid < PT) gflat_s[tid] = (tbase + tid < P) ? g_flat[tbase + tid] : -1;

    uint32_t sf_s0 = (uint32_t)__cvta_generic_to_shared(sfb0);
    uint32_t sf_s1 = (uint32_t)__cvta_generic_to_shared(sfb1);

    auto stage = [&](int ch, int bsel) {
        const char* sg = (const char*)(g_sfD + (size_t)(ch * KC) * SS)
                       + (size_t)tid * 16;
        uint32_t sfs = (bsel ? sf_s1 : sf_s0) + (uint32_t)(tid * 16);
#pragma unroll
        for (int j = 0; j < (KC * SS * 8) / (TPB2 * 16); j++)   // 8
            cp_async16(sfs + (uint32_t)(j * TPB2 * 16),
                       sg + (size_t)j * TPB2 * 16);
    };

    stage(0, 0);
    asm volatile("cp.async.commit_group;" ::: "memory");
    __syncthreads();                       // gflat_s/scat ready

    const int tp = tid & 15;               // two proposal quads
    const int ts = tid >> 4;               // 4 sentences ts*4..
    const int q0 = tp * 4;                 // quad 0 start (proposal in tile)
    const int q1 = 64 + tp * 4;            // quad 1 start
    const int g0raw = gflat_s[q0];
    const int g1raw = gflat_s[q1];
    const int f0 = g0raw ^ (g0raw >> 31);  // decode: flat base (mult of 4)
    const int f1 = g1raw ^ (g1raw >> 31);
    const size_t vbase = (size_t)b * CC * NN;
    const float* vp0 = video + vbase + f0;
    const float* vp1 = video + vbase + f1;

    unsigned long long acc[4][4];          // [ppair][s]
#pragma unroll
    for (int j = 0; j < 4; j++)
#pragma unroll
        for (int i = 0; i < 4; i++) acc[j][i] = 0ull;
    unsigned long long ssq2[4];
#pragma unroll
    for (int j = 0; j < 4; j++) ssq2[j] = 0ull;

#pragma unroll 1
    for (int ch = 0; ch < CHN; ch++) {
        const int cur = ch & 1;
        if (ch + 1 < CHN) {
            stage(ch + 1, cur ^ 1);
            asm volatile("cp.async.commit_group;" ::: "memory");
            asm volatile("cp.async.wait_group 1;" ::: "memory");
        } else {
            asm volatile("cp.async.wait_group 0;" ::: "memory");
        }
        __syncthreads();

        const unsigned long long* sfd = cur ? sfb1 : sfb0;
        const size_t coff = (size_t)(ch * KC) * NN;
#pragma unroll 8
        for (int k = 0; k < KC; k++) {
            ulonglong2 va0 = __ldg((const ulonglong2*)(vp0 + coff + (size_t)k * NN));
            ulonglong2 va1 = __ldg((const ulonglong2*)(vp1 + coff + (size_t)k * NN));

            const unsigned long long* srow = sfd + k * SS + ts * 4;
            ulonglong2 s0 = *reinterpret_cast<const ulonglong2*>(srow);
            ulonglong2 s1 = *reinterpret_cast<const ulonglong2*>(srow + 2);

            ffma2(ssq2[0], va0.x, va0.x);
            ffma2(ssq2[1], va0.y, va0.y);
            ffma2(ssq2[2], va1.x, va1.x);
            ffma2(ssq2[3], va1.y, va1.y);
#pragma unroll
            for (int j = 0; j < 4; j++) {
                unsigned long long vv = j == 0 ? va0.x : j == 1 ? va0.y
                                      : j == 2 ? va1.x : va1.y;
                ffma2(acc[j][0], s0.x, vv);
                ffma2(acc[j][1], s0.y, vv);
                ffma2(acc[j][2], s1.x, vv);
                ffma2(acc[j][3], s1.y, vv);
            }
        }
        __syncthreads();
    }

    // per-proposal 1/norm * (1/t); pair j -> proposals:
    //   j<2: q0+2j, q0+2j+1      j>=2: q1+2(j-2), q1+2(j-2)+1
    float inv[8];
    int   gg[8];
#pragma unroll
    for (int j = 0; j < 4; j++) {
        int pj = (j < 2) ? (q0 + 2 * j) : (q1 + 2 * (j - 2));
        inv[2 * j]     = rsqrtf(fmaxf(unpack_lo(ssq2[j]), 1e-24f)) * INV_T;
        inv[2 * j + 1] = rsqrtf(fmaxf(unpack_hi(ssq2[j]), 1e-24f)) * INV_T;
        gg[2 * j]      = gflat_s[pj];
        gg[2 * j + 1]  = gflat_s[pj + 1];
    }

    const int item = b * MAXT + tile;
#pragma unroll 1
    for (int i = 0; i < 4; i++) {
        int s = ts * 4 + i;
        bool same = (scat[s] == b);
        float esum = 0.0f;
#pragma unroll
        for (int j = 0; j < 4; j++) {
            int gA = gg[2 * j], gB = gg[2 * j + 1];
            if (gA >= 0) {
                bool pos = same && (iou[s * NN + gA] > 0.5f);
                if (!pos) esum += __expf(unpack_lo(acc[j][i]) * inv[2 * j]);
            }
            if (gB >= 0) {
                bool pos = same && (iou[s * NN + gB] > 0.5f);
                if (!pos) esum += __expf(unpack_hi(acc[j][i]) * inv[2 * j + 1]);
            }
        }
        // reduce across the 16 proposal-groups (width-16 shuffle segments)
#pragma unroll
        for (int off = 8; off; off >>= 1)
            esum += __shfl_down_sync(0xffffffffu, esum, off, 16);
        if (tp == 0) g_partial[(size_t)s * NITEM + item] = esum;
    }
}

// ---------------- tail: reduce partials + topk dots (fused) ----------------
__global__ void tail_kernel(const float* __restrict__ video) {
    int s = blockIdx.x, t = threadIdx.x;   // SS blocks x 256 threads

    // part 1: deterministic reduction of inter-query partials (coalesced)
    {
        int used = (g_P + PT - 1) / PT;    // live tiles per video
        __shared__ float sm[256];
        float sum = 0.0f;
        const float* row = &g_partial[(size_t)s * NITEM];
        for (int i = t; i < NITEM; i += 256) {
            int tl = i % MAXT;
            if (tl < used) sum += row[i];
        }
        sm[t] = sum;
        __syncthreads();
        for (int st = 128; st > 0; st >>= 1) {
            if (t < st) sm[t] += sm[t + st];
            __syncthreads();
        }
        if (t == 0) g_negsum[s] = sm[0];
        __syncthreads();
    }

    // part 2: A[s][t] = dot(normalized topk proposal of s, sf[t])
    {
        __shared__ float tv[CC];
        __shared__ float rs[CC];
        int b = g_scatter[s];
        int g = g_pstar[s];
        float v = video[((size_t)(b * CC + t)) * NN + g];
        rs[t] = v * v;
        __syncthreads();
        for (int st = 128; st > 0; st >>= 1) {
            if (t < st) rs[t] += rs[t + st];
            __syncthreads();
        }
        float inv = 1.0f / fmaxf(sqrtf(rs[0]), EPSN);
        tv[t] = v * inv;
        __syncthreads();
        int lane = t & 31, wrp = t >> 5;
        for (int q = wrp; q < SS; q += 8) {
            float d = 0.0f;
            for (int c = lane; c < CC; c += 32) d += g_sf[q * CC + c] * tv[c];
#pragma unroll
            for (int off = 16; off; off >>= 1)
                d += __shfl_down_sync(0xffffffffu, d, off);
            if (lane == 0) g_A[s * SS + q] = d;
        }
    }
}

// ---------------- final losses ----------------
__global__ void finalize(float* __restrict__ out) {
    __shared__ float l1[SS], l2[SS];
    int s = threadIdx.x;   // SS threads
    float pos = g_A[s * SS + s];
    float nsv = 0.0f;
    for (int u = 0; u < SS; u++)
        if (u != s) nsv += expf(g_A[s * SS + u] * INV_T);
    float pe = expf(pos * INV_T);
    float lv = -(pos * INV_T - logf(pe + nsv));
    float lq = -(pos * INV_T - logf(pe + g_negsum[s]));
    l1[s] = lv; l2[s] = lq;
    __syncthreads();
    for (int st = 32; st > 0; st >>= 1) {
        if (s < st) { l1[s] += l1[s + st]; l2[s] += l2[s + st]; }
        __syncthreads();
    }
    if (s == 0) {
        out[0] = l1[0] / (float)SS;  // loss_inter_video
        out[1] = l2[0] / (float)SS;  // loss_inter_query
    }
}

// ---------------- launcher ----------------
extern "C" void kernel_launch(void* const* d_in, const int* in_sizes, int n_in,
                              void* d_out, int out_size) {
    const float*         video = (const float*)d_in[0];         // [B,C,N,N]
    const float*         sents = (const float*)d_in[1];         // [S,C]
    const int*           ntgt  = (const int*)d_in[2];           // [B]
    const float*         iou   = (const float*)d_in[3];         // [S,N,N]
    const unsigned char* mask  = (const unsigned char*)d_in[4]; // [N,N] bool
    float* out = (float*)d_out;

    const int smem_bytes = 2 * KC * SS * 8;                     // 64 KB
    cudaFuncSetAttribute(score_kernel,
                         cudaFuncAttributeMaxDynamicSharedMemorySize, smem_bytes);

    setup_kernel<<<1, 1024>>>(mask, ntgt);
    prep_kernel<<<SS, 256>>>(sents, iou);
    dim3 grid(MAXT, BB);
    score_kernel<<<grid, TPB2, smem_bytes>>>(video, iou);
    tail_kernel<<<SS, 256>>>(video);
    finalize<<<1, SS>>>(out);
}